// round 4
// baseline (speedup 1.0000x reference)
#include <cuda_runtime.h>
#include <cuda_bf16.h>
#include <math.h>

// Problem constants
#define BB 16
#define MM 256
#define TT 128
#define DD 512
#define HH 8
#define LL 4
#define VV 32000
#define HD 64
#define BT (BB*TT)     // 2048
#define BM_ROWS (BB*MM) // 4096

// ---------------- scratch (static device globals; no allocation allowed) ---
__device__ float g_x[BT*DD];        // residual stream [2048,512]
__device__ float g_h[BT*DD];        // LN output
__device__ float g_attn[BT*DD];     // merged attention output
__device__ float g_q[BT*DD];        // cross-attn query
__device__ float g_qkv[BT*3*DD];    // self-attn qkv [2048,1536]
__device__ float g_kv[BM_ROWS*2*DD];// cross kv proj [4096,1024]
__device__ float g_ffn[BT*4*DD];    // ffn hidden [2048,2048]
__device__ int   g_is64;

// ---------------- targets dtype detection (int32 vs int64) ----------------
// If targets is int64 (values < 2^31), every high 32-bit word is 0.
// If int32, the words at odd indices are random token ids (won't all be 0).
__global__ void detect_kernel(const int* t) {
    __shared__ int any;
    if (threadIdx.x == 0) any = 0;
    __syncthreads();
    int local = 0;
    for (int i = threadIdx.x; i < BT/2; i += blockDim.x)
        if (t[2*i + 1] != 0) local = 1;
    if (local) atomicOr(&any, 1);
    __syncthreads();
    if (threadIdx.x == 0) g_is64 = (any == 0) ? 1 : 0;
}

// ---------------- embedding -----------------------------------------------
__global__ void embed_kernel(const void* __restrict__ targets,
                             const float* __restrict__ tok,
                             const float* __restrict__ pos,
                             float* __restrict__ x) {
    int idx = blockIdx.x * blockDim.x + threadIdx.x;
    if (idx >= BT*DD) return;
    int d  = idx & (DD-1);
    int bt = idx >> 9;          // /512
    int t  = bt & (TT-1);
    int b  = bt >> 7;           // /128
    long long token;
    if (t == 0) token = VV;     // BOS row = 32000
    else {
        int ti = b*TT + t - 1;
        token = g_is64 ? ((const long long*)targets)[ti]
                       : (long long)((const int*)targets)[ti];
    }
    x[idx] = tok[(size_t)token*DD + d] + pos[(size_t)t*DD + d];
}

// ---------------- LayerNorm (row length 512) -------------------------------
__global__ void ln_kernel(const float* __restrict__ x,
                          const float* __restrict__ g,
                          const float* __restrict__ bta,
                          float* __restrict__ o) {
    int r = blockIdx.x;
    const float* xr = x + (size_t)r * DD;
    float* orow = o + (size_t)r * DD;
    int tid = threadIdx.x;                // 256
    int w = tid >> 5, lane = tid & 31;
    __shared__ float red[8];

    float s = xr[tid] + xr[tid + 256];
    #pragma unroll
    for (int off = 16; off > 0; off >>= 1) s += __shfl_xor_sync(~0u, s, off);
    if (lane == 0) red[w] = s;
    __syncthreads();
    float tot = 0.f;
    #pragma unroll
    for (int i = 0; i < 8; i++) tot += red[i];
    float mean = tot * (1.0f / DD);
    __syncthreads();

    float d0 = xr[tid] - mean, d1 = xr[tid + 256] - mean;
    float v = d0*d0 + d1*d1;
    #pragma unroll
    for (int off = 16; off > 0; off >>= 1) v += __shfl_xor_sync(~0u, v, off);
    if (lane == 0) red[w] = v;
    __syncthreads();
    float vt = 0.f;
    #pragma unroll
    for (int i = 0; i < 8; i++) vt += red[i];
    float inv = rsqrtf(vt * (1.0f / DD) + 1e-5f);

    orow[tid]       = d0 * inv * g[tid]       + bta[tid];
    orow[tid + 256] = d1 * inv * g[tid + 256] + bta[tid + 256];
}

// ---------------- tiled SGEMM: C = A[M,K] @ B[K,N] (+bias)(+res)(gelu) ------
// BMt=BNt=64, BKt=16, 256 threads, 4x4 per-thread micro-tile.
// All M % 64 == 0, N % 64 == 0, K % 16 == 0 for this problem.
#define BMt 64
#define BNt 64
#define BKt 16

__device__ __forceinline__ float gelu_exact(float v) {
    return 0.5f * v * (1.0f + erff(v * 0.70710678118654752f));
}

template<int EPI>  // 0: +bias, 1: +bias+residual, 2: gelu(+bias)
__global__ void sgemm_kernel(const float* __restrict__ A,
                             const float* __restrict__ B,
                             const float* __restrict__ bias,
                             const float* __restrict__ R,
                             float* __restrict__ C,
                             int M, int N, int K) {
    __shared__ float  As[BKt][BMt + 4];
    __shared__ float4 Bs[BKt][BNt/4];
    int tid = threadIdx.x;          // 256
    int tx = tid & 15, ty = tid >> 4;
    int m0 = blockIdx.y * BMt, n0 = blockIdx.x * BNt;

    const float4* A4 = (const float4*)A;
    const float4* B4 = (const float4*)B;
    int K4 = K >> 2, N4 = N >> 2;

    int am = tid >> 2, akq = tid & 3;   // A: row am (0..63), float4 col akq
    int bk = tid >> 4, bn4 = tid & 15;  // B: row bk (0..15), float4 col bn4

    float acc[4][4] = {};

    for (int k0 = 0; k0 < K; k0 += BKt) {
        float4 av = A4[(size_t)(m0 + am) * K4 + (k0 >> 2) + akq];
        As[akq*4 + 0][am] = av.x;
        As[akq*4 + 1][am] = av.y;
        As[akq*4 + 2][am] = av.z;
        As[akq*4 + 3][am] = av.w;
        Bs[bk][bn4] = B4[(size_t)(k0 + bk) * N4 + (n0 >> 2) + bn4];
        __syncthreads();
        #pragma unroll
        for (int kk = 0; kk < BKt; kk++) {
            float a0 = As[kk][ty*4+0], a1 = As[kk][ty*4+1];
            float a2 = As[kk][ty*4+2], a3 = As[kk][ty*4+3];
            float4 bv = Bs[kk][tx];
            acc[0][0] += a0*bv.x; acc[0][1] += a0*bv.y; acc[0][2] += a0*bv.z; acc[0][3] += a0*bv.w;
            acc[1][0] += a1*bv.x; acc[1][1] += a1*bv.y; acc[1][2] += a1*bv.z; acc[1][3] += a1*bv.w;
            acc[2][0] += a2*bv.x; acc[2][1] += a2*bv.y; acc[2][2] += a2*bv.z; acc[2][3] += a2*bv.w;
            acc[3][0] += a3*bv.x; acc[3][1] += a3*bv.y; acc[3][2] += a3*bv.z; acc[3][3] += a3*bv.w;
        }
        __syncthreads();
    }

    float4 bi = ((const float4*)bias)[(n0 >> 2) + tx];
    #pragma unroll
    for (int i = 0; i < 4; i++) {
        int row = m0 + ty*4 + i;
        float4 v;
        v.x = acc[i][0] + bi.x; v.y = acc[i][1] + bi.y;
        v.z = acc[i][2] + bi.z; v.w = acc[i][3] + bi.w;
        if (EPI == 1) {
            float4 rv = ((const float4*)R)[(size_t)row * N4 + (n0 >> 2) + tx];
            v.x += rv.x; v.y += rv.y; v.z += rv.z; v.w += rv.w;
        } else if (EPI == 2) {
            v.x = gelu_exact(v.x); v.y = gelu_exact(v.y);
            v.z = gelu_exact(v.z); v.w = gelu_exact(v.w);
        }
        ((float4*)C)[(size_t)row * N4 + (n0 >> 2) + tx] = v;
    }
}

// ---------------- self-attention (causal, T=128 keys) ----------------------
// grid(T, B*H), 128 threads. qkv row layout: [q(512) k(512) v(512)].
__global__ void self_attn_kernel(const float* __restrict__ qkv,
                                 float* __restrict__ out) {
    int q = blockIdx.x;
    int b = blockIdx.y >> 3, h = blockIdx.y & 7;
    int tid = threadIdx.x;              // 128
    int w = tid >> 5, lane = tid & 31;

    __shared__ float sQ[HD];
    __shared__ float sc[TT];
    __shared__ float red[4];
    __shared__ float part[2][HD];

    const float* Qp = qkv + ((size_t)(b*TT + q)) * (3*DD) + h*HD;
    if (tid < HD) sQ[tid] = Qp[tid];
    __syncthreads();

    float s;
    if (tid <= q) {
        const float* Kp = qkv + ((size_t)(b*TT + tid)) * (3*DD) + DD + h*HD;
        float a = 0.f;
        #pragma unroll
        for (int d = 0; d < HD; d++) a += sQ[d] * Kp[d];
        s = a * 0.125f;                 // 1/sqrt(64)
    } else s = -1e9f;

    float m = s;
    #pragma unroll
    for (int off = 16; off > 0; off >>= 1) m = fmaxf(m, __shfl_xor_sync(~0u, m, off));
    if (lane == 0) red[w] = m;
    __syncthreads();
    float gm = fmaxf(fmaxf(red[0], red[1]), fmaxf(red[2], red[3]));
    __syncthreads();
    float e = expf(s - gm);
    float su = e;
    #pragma unroll
    for (int off = 16; off > 0; off >>= 1) su += __shfl_xor_sync(~0u, su, off);
    if (lane == 0) red[w] = su;
    sc[tid] = e;
    __syncthreads();
    float gs = red[0] + red[1] + red[2] + red[3];

    // AV: thread (d, half); each half covers 64 keys
    int d = tid & 63, half = tid >> 6;
    float a = 0.f;
    int kbase = half * 64;
    for (int kk = 0; kk < 64; kk++) {
        const float* Vp = qkv + ((size_t)(b*TT + kbase + kk)) * (3*DD) + 2*DD + h*HD;
        a += sc[kbase + kk] * Vp[d];
    }
    part[half][d] = a;
    __syncthreads();
    if (tid < HD)
        out[((size_t)(b*TT + q)) * DD + h*HD + tid] =
            (part[0][tid] + part[1][tid]) / gs;
}

// ---------------- cross-attention (M=256 keys, no mask) --------------------
// grid(T, B*H), 256 threads. kv row layout: [k(512) v(512)].
__global__ void cross_attn_kernel(const float* __restrict__ qbuf,
                                  const float* __restrict__ kv,
                                  float* __restrict__ out) {
    int q = blockIdx.x;
    int b = blockIdx.y >> 3, h = blockIdx.y & 7;
    int tid = threadIdx.x;              // 256
    int w = tid >> 5, lane = tid & 31;

    __shared__ float sQ[HD];
    __shared__ float sc[MM];
    __shared__ float red[8];
    __shared__ float part[4][HD];

    if (tid < HD) sQ[tid] = qbuf[((size_t)(b*TT + q)) * DD + h*HD + tid];
    __syncthreads();

    const float* Kp = kv + ((size_t)(b*MM + tid)) * (2*DD) + h*HD;
    float a = 0.f;
    #pragma unroll
    for (int d = 0; d < HD; d++) a += sQ[d] * Kp[d];
    float s = a * 0.125f;

    float m = s;
    #pragma unroll
    for (int off = 16; off > 0; off >>= 1) m = fmaxf(m, __shfl_xor_sync(~0u, m, off));
    if (lane == 0) red[w] = m;
    __syncthreads();
    float gm = red[0];
    #pragma unroll
    for (int i = 1; i < 8; i++) gm = fmaxf(gm, red[i]);
    __syncthreads();
    float e = expf(s - gm);
    float su = e;
    #pragma unroll
    for (int off = 16; off > 0; off >>= 1) su += __shfl_xor_sync(~0u, su, off);
    if (lane == 0) red[w] = su;
    sc[tid] = e;
    __syncthreads();
    float gs = 0.f;
    #pragma unroll
    for (int i = 0; i < 8; i++) gs += red[i];

    int d = tid & 63, qt = tid >> 6;
    float av = 0.f;
    int kbase = qt * 64;
    for (int kk = 0; kk < 64; kk++) {
        const float* Vp = kv + ((size_t)(b*MM + kbase + kk)) * (2*DD) + DD + h*HD;
        av += sc[kbase + kk] * Vp[d];
    }
    part[qt][d] = av;
    __syncthreads();
    if (tid < HD)
        out[((size_t)(b*TT + q)) * DD + h*HD + tid] =
            (part[0][tid] + part[1][tid] + part[2][tid] + part[3][tid]) / gs;
}

// ---------------- host orchestration ---------------------------------------
static inline void run_gemm(int epi, const float* A, const float* B,
                            const float* bias, const float* R, float* C,
                            int M, int N, int K) {
    dim3 grid(N / BNt, M / BMt);
    if (epi == 0)      sgemm_kernel<0><<<grid, 256>>>(A, B, bias, R, C, M, N, K);
    else if (epi == 1) sgemm_kernel<1><<<grid, 256>>>(A, B, bias, R, C, M, N, K);
    else               sgemm_kernel<2><<<grid, 256>>>(A, B, bias, R, C, M, N, K);
}

extern "C" void kernel_launch(void* const* d_in, const int* in_sizes, int n_in,
                              void* d_out, int out_size) {
    const float* memory  = (const float*)d_in[0];
    const void*  targets = d_in[1];
    const float* tok_emb = (const float*)d_in[2];
    const float* pos_emb = (const float*)d_in[3];
    const float* sa_qkv_w = (const float*)d_in[4];
    const float* sa_qkv_b = (const float*)d_in[5];
    const float* sa_out_w = (const float*)d_in[6];
    const float* sa_out_b = (const float*)d_in[7];
    const float* ca_q_w   = (const float*)d_in[8];
    const float* ca_q_b   = (const float*)d_in[9];
    const float* ca_kv_w  = (const float*)d_in[10];
    const float* ca_kv_b  = (const float*)d_in[11];
    const float* ca_out_w = (const float*)d_in[12];
    const float* ca_out_b = (const float*)d_in[13];
    const float* ffn1_w   = (const float*)d_in[14];
    const float* ffn1_b   = (const float*)d_in[15];
    const float* ffn2_w   = (const float*)d_in[16];
    const float* ffn2_b   = (const float*)d_in[17];
    const float* ln1_g = (const float*)d_in[18];
    const float* ln1_b = (const float*)d_in[19];
    const float* ln2_g = (const float*)d_in[20];
    const float* ln2_b = (const float*)d_in[21];
    const float* ln3_g = (const float*)d_in[22];
    const float* ln3_b = (const float*)d_in[23];
    const float* normf_g = (const float*)d_in[24];
    const float* normf_b = (const float*)d_in[25];
    const float* out_w = (const float*)d_in[26];
    const float* out_b = (const float*)d_in[27];
    float* out = (float*)d_out;

    float *x, *h, *attn, *qb, *qkv, *kv, *ffn;
    cudaGetSymbolAddress((void**)&x,    g_x);
    cudaGetSymbolAddress((void**)&h,    g_h);
    cudaGetSymbolAddress((void**)&attn, g_attn);
    cudaGetSymbolAddress((void**)&qb,   g_q);
    cudaGetSymbolAddress((void**)&qkv,  g_qkv);
    cudaGetSymbolAddress((void**)&kv,   g_kv);
    cudaGetSymbolAddress((void**)&ffn,  g_ffn);

    detect_kernel<<<1, 256>>>((const int*)targets);
    embed_kernel<<<(BT*DD + 255) / 256, 256>>>(targets, tok_emb, pos_emb, x);

    dim3 agrid(TT, BB*HH);

    for (int l = 0; l < LL; l++) {
        // ---- self-attention ----
        ln_kernel<<<BT, 256>>>(x, ln1_g + l*DD, ln1_b + l*DD, h);
        run_gemm(0, h, sa_qkv_w + (size_t)l*DD*3*DD, sa_qkv_b + (size_t)l*3*DD,
                 nullptr, qkv, BT, 3*DD, DD);
        self_attn_kernel<<<agrid, 128>>>(qkv, attn);
        run_gemm(1, attn, sa_out_w + (size_t)l*DD*DD, sa_out_b + (size_t)l*DD,
                 x, x, BT, DD, DD);
        // ---- cross-attention ----
        ln_kernel<<<BT, 256>>>(x, ln2_g + l*DD, ln2_b + l*DD, h);
        run_gemm(0, h, ca_q_w + (size_t)l*DD*DD, ca_q_b + (size_t)l*DD,
                 nullptr, qb, BT, DD, DD);
        run_gemm(0, memory, ca_kv_w + (size_t)l*DD*2*DD, ca_kv_b + (size_t)l*2*DD,
                 nullptr, kv, BM_ROWS, 2*DD, DD);
        cross_attn_kernel<<<agrid, 256>>>(qb, kv, attn);
        run_gemm(1, attn, ca_out_w + (size_t)l*DD*DD, ca_out_b + (size_t)l*DD,
                 x, x, BT, DD, DD);
        // ---- FFN ----
        ln_kernel<<<BT, 256>>>(x, ln3_g + l*DD, ln3_b + l*DD, h);
        run_gemm(2, h, ffn1_w + (size_t)l*DD*4*DD, ffn1_b + (size_t)l*4*DD,
                 nullptr, ffn, BT, 4*DD, DD);
        run_gemm(1, ffn, ffn2_w + (size_t)l*4*DD*DD, ffn2_b + (size_t)l*DD,
                 x, x, BT, DD, 4*DD);
    }

    // ---- final LN + vocab head ----
    ln_kernel<<<BT, 256>>>(x, normf_g, normf_b, h);
    run_gemm(0, h, out_w, out_b, nullptr, out, BT, VV, DD);
}

// round 5
// speedup vs baseline: 1.0012x; 1.0012x over previous
#include <cuda_runtime.h>
#include <cuda_bf16.h>
#include <math.h>

// Problem constants
#define BB 16
#define MM 256
#define TT 128
#define DD 512
#define HH 8
#define LL 4
#define VV 32000
#define HD 64
#define BT (BB*TT)     // 2048
#define BM_ROWS (BB*MM) // 4096

// ---------------- scratch (static device globals; no allocation allowed) ---
__device__ float g_x[BT*DD];        // residual stream [2048,512]
__device__ float g_h[BT*DD];        // LN output
__device__ float g_attn[BT*DD];     // merged attention output
__device__ float g_q[BT*DD];        // cross-attn query
__device__ float g_qkv[BT*3*DD];    // self-attn qkv [2048,1536]
__device__ float g_kv[BM_ROWS*2*DD];// cross kv proj [4096,1024]
__device__ float g_ffn[BT*4*DD];    // ffn hidden [2048,2048]
__device__ int   g_is64;

// ---------------- targets dtype detection (int32 vs int64) ----------------
// If targets is int64 (values < 2^31), every high 32-bit word is 0.
// If int32, the words at odd indices are random token ids (won't all be 0).
__global__ void detect_kernel(const int* t) {
    __shared__ int any;
    if (threadIdx.x == 0) any = 0;
    __syncthreads();
    int local = 0;
    for (int i = threadIdx.x; i < BT/2; i += blockDim.x)
        if (t[2*i + 1] != 0) local = 1;
    if (local) atomicOr(&any, 1);
    __syncthreads();
    if (threadIdx.x == 0) g_is64 = (any == 0) ? 1 : 0;
}

// ---------------- embedding -----------------------------------------------
__global__ void embed_kernel(const void* __restrict__ targets,
                             const float* __restrict__ tok,
                             const float* __restrict__ pos,
                             float* __restrict__ x) {
    int idx = blockIdx.x * blockDim.x + threadIdx.x;
    if (idx >= BT*DD) return;
    int d  = idx & (DD-1);
    int bt = idx >> 9;          // /512
    int t  = bt & (TT-1);
    int b  = bt >> 7;           // /128
    long long token;
    if (t == 0) token = VV;     // BOS row = 32000
    else {
        int ti = b*TT + t - 1;
        token = g_is64 ? ((const long long*)targets)[ti]
                       : (long long)((const int*)targets)[ti];
    }
    x[idx] = tok[(size_t)token*DD + d] + pos[(size_t)t*DD + d];
}

// ---------------- LayerNorm (row length 512) -------------------------------
__global__ void ln_kernel(const float* __restrict__ x,
                          const float* __restrict__ g,
                          const float* __restrict__ bta,
                          float* __restrict__ o) {
    int r = blockIdx.x;
    const float* xr = x + (size_t)r * DD;
    float* orow = o + (size_t)r * DD;
    int tid = threadIdx.x;                // 256
    int w = tid >> 5, lane = tid & 31;
    __shared__ float red[8];

    float s = xr[tid] + xr[tid + 256];
    #pragma unroll
    for (int off = 16; off > 0; off >>= 1) s += __shfl_xor_sync(~0u, s, off);
    if (lane == 0) red[w] = s;
    __syncthreads();
    float tot = 0.f;
    #pragma unroll
    for (int i = 0; i < 8; i++) tot += red[i];
    float mean = tot * (1.0f / DD);
    __syncthreads();

    float d0 = xr[tid] - mean, d1 = xr[tid + 256] - mean;
    float v = d0*d0 + d1*d1;
    #pragma unroll
    for (int off = 16; off > 0; off >>= 1) v += __shfl_xor_sync(~0u, v, off);
    if (lane == 0) red[w] = v;
    __syncthreads();
    float vt = 0.f;
    #pragma unroll
    for (int i = 0; i < 8; i++) vt += red[i];
    float inv = rsqrtf(vt * (1.0f / DD) + 1e-5f);

    orow[tid]       = d0 * inv * g[tid]       + bta[tid];
    orow[tid + 256] = d1 * inv * g[tid + 256] + bta[tid + 256];
}

// ---------------- tiled SGEMM: C = A[M,K] @ B[K,N] (+bias)(+res)(gelu) ------
// BMt=BNt=64, BKt=16, 256 threads, 4x4 per-thread micro-tile.
// All M % 64 == 0, N % 64 == 0, K % 16 == 0 for this problem.
#define BMt 64
#define BNt 64
#define BKt 16

__device__ __forceinline__ float gelu_exact(float v) {
    return 0.5f * v * (1.0f + erff(v * 0.70710678118654752f));
}

template<int EPI>  // 0: +bias, 1: +bias+residual, 2: gelu(+bias)
__global__ void sgemm_kernel(const float* __restrict__ A,
                             const float* __restrict__ B,
                             const float* __restrict__ bias,
                             const float* __restrict__ R,
                             float* __restrict__ C,
                             int M, int N, int K) {
    __shared__ float  As[BKt][BMt + 4];
    __shared__ float4 Bs[BKt][BNt/4];
    int tid = threadIdx.x;          // 256
    int tx = tid & 15, ty = tid >> 4;
    int m0 = blockIdx.y * BMt, n0 = blockIdx.x * BNt;

    const float4* A4 = (const float4*)A;
    const float4* B4 = (const float4*)B;
    int K4 = K >> 2, N4 = N >> 2;

    int am = tid >> 2, akq = tid & 3;   // A: row am (0..63), float4 col akq
    int bk = tid >> 4, bn4 = tid & 15;  // B: row bk (0..15), float4 col bn4

    float acc[4][4] = {};

    for (int k0 = 0; k0 < K; k0 += BKt) {
        float4 av = A4[(size_t)(m0 + am) * K4 + (k0 >> 2) + akq];
        As[akq*4 + 0][am] = av.x;
        As[akq*4 + 1][am] = av.y;
        As[akq*4 + 2][am] = av.z;
        As[akq*4 + 3][am] = av.w;
        Bs[bk][bn4] = B4[(size_t)(k0 + bk) * N4 + (n0 >> 2) + bn4];
        __syncthreads();
        #pragma unroll
        for (int kk = 0; kk < BKt; kk++) {
            float a0 = As[kk][ty*4+0], a1 = As[kk][ty*4+1];
            float a2 = As[kk][ty*4+2], a3 = As[kk][ty*4+3];
            float4 bv = Bs[kk][tx];
            acc[0][0] += a0*bv.x; acc[0][1] += a0*bv.y; acc[0][2] += a0*bv.z; acc[0][3] += a0*bv.w;
            acc[1][0] += a1*bv.x; acc[1][1] += a1*bv.y; acc[1][2] += a1*bv.z; acc[1][3] += a1*bv.w;
            acc[2][0] += a2*bv.x; acc[2][1] += a2*bv.y; acc[2][2] += a2*bv.z; acc[2][3] += a2*bv.w;
            acc[3][0] += a3*bv.x; acc[3][1] += a3*bv.y; acc[3][2] += a3*bv.z; acc[3][3] += a3*bv.w;
        }
        __syncthreads();
    }

    float4 bi = ((const float4*)bias)[(n0 >> 2) + tx];
    #pragma unroll
    for (int i = 0; i < 4; i++) {
        int row = m0 + ty*4 + i;
        float4 v;
        v.x = acc[i][0] + bi.x; v.y = acc[i][1] + bi.y;
        v.z = acc[i][2] + bi.z; v.w = acc[i][3] + bi.w;
        if (EPI == 1) {
            float4 rv = ((const float4*)R)[(size_t)row * N4 + (n0 >> 2) + tx];
            v.x += rv.x; v.y += rv.y; v.z += rv.z; v.w += rv.w;
        } else if (EPI == 2) {
            v.x = gelu_exact(v.x); v.y = gelu_exact(v.y);
            v.z = gelu_exact(v.z); v.w = gelu_exact(v.w);
        }
        ((float4*)C)[(size_t)row * N4 + (n0 >> 2) + tx] = v;
    }
}

// ---------------- self-attention (causal, T=128 keys) ----------------------
// grid(T, B*H), 128 threads. qkv row layout: [q(512) k(512) v(512)].
__global__ void self_attn_kernel(const float* __restrict__ qkv,
                                 float* __restrict__ out) {
    int q = blockIdx.x;
    int b = blockIdx.y >> 3, h = blockIdx.y & 7;
    int tid = threadIdx.x;              // 128
    int w = tid >> 5, lane = tid & 31;

    __shared__ float sQ[HD];
    __shared__ float sc[TT];
    __shared__ float red[4];
    __shared__ float part[2][HD];

    const float* Qp = qkv + ((size_t)(b*TT + q)) * (3*DD) + h*HD;
    if (tid < HD) sQ[tid] = Qp[tid];
    __syncthreads();

    float s;
    if (tid <= q) {
        const float* Kp = qkv + ((size_t)(b*TT + tid)) * (3*DD) + DD + h*HD;
        float a = 0.f;
        #pragma unroll
        for (int d = 0; d < HD; d++) a += sQ[d] * Kp[d];
        s = a * 0.125f;                 // 1/sqrt(64)
    } else s = -1e9f;

    float m = s;
    #pragma unroll
    for (int off = 16; off > 0; off >>= 1) m = fmaxf(m, __shfl_xor_sync(~0u, m, off));
    if (lane == 0) red[w] = m;
    __syncthreads();
    float gm = fmaxf(fmaxf(red[0], red[1]), fmaxf(red[2], red[3]));
    __syncthreads();
    float e = expf(s - gm);
    float su = e;
    #pragma unroll
    for (int off = 16; off > 0; off >>= 1) su += __shfl_xor_sync(~0u, su, off);
    if (lane == 0) red[w] = su;
    sc[tid] = e;
    __syncthreads();
    float gs = red[0] + red[1] + red[2] + red[3];

    // AV: thread (d, half); each half covers 64 keys
    int d = tid & 63, half = tid >> 6;
    float a = 0.f;
    int kbase = half * 64;
    for (int kk = 0; kk < 64; kk++) {
        const float* Vp = qkv + ((size_t)(b*TT + kbase + kk)) * (3*DD) + 2*DD + h*HD;
        a += sc[kbase + kk] * Vp[d];
    }
    part[half][d] = a;
    __syncthreads();
    if (tid < HD)
        out[((size_t)(b*TT + q)) * DD + h*HD + tid] =
            (part[0][tid] + part[1][tid]) / gs;
}

// ---------------- cross-attention (M=256 keys, no mask) --------------------
// grid(T, B*H), 256 threads. kv row layout: [k(512) v(512)].
__global__ void cross_attn_kernel(const float* __restrict__ qbuf,
                                  const float* __restrict__ kv,
                                  float* __restrict__ out) {
    int q = blockIdx.x;
    int b = blockIdx.y >> 3, h = blockIdx.y & 7;
    int tid = threadIdx.x;              // 256
    int w = tid >> 5, lane = tid & 31;

    __shared__ float sQ[HD];
    __shared__ float sc[MM];
    __shared__ float red[8];
    __shared__ float part[4][HD];

    if (tid < HD) sQ[tid] = qbuf[((size_t)(b*TT + q)) * DD + h*HD + tid];
    __syncthreads();

    const float* Kp = kv + ((size_t)(b*MM + tid)) * (2*DD) + h*HD;
    float a = 0.f;
    #pragma unroll
    for (int d = 0; d < HD; d++) a += sQ[d] * Kp[d];
    float s = a * 0.125f;

    float m = s;
    #pragma unroll
    for (int off = 16; off > 0; off >>= 1) m = fmaxf(m, __shfl_xor_sync(~0u, m, off));
    if (lane == 0) red[w] = m;
    __syncthreads();
    float gm = red[0];
    #pragma unroll
    for (int i = 1; i < 8; i++) gm = fmaxf(gm, red[i]);
    __syncthreads();
    float e = expf(s - gm);
    float su = e;
    #pragma unroll
    for (int off = 16; off > 0; off >>= 1) su += __shfl_xor_sync(~0u, su, off);
    if (lane == 0) red[w] = su;
    sc[tid] = e;
    __syncthreads();
    float gs = 0.f;
    #pragma unroll
    for (int i = 0; i < 8; i++) gs += red[i];

    int d = tid & 63, qt = tid >> 6;
    float av = 0.f;
    int kbase = qt * 64;
    for (int kk = 0; kk < 64; kk++) {
        const float* Vp = kv + ((size_t)(b*MM + kbase + kk)) * (2*DD) + DD + h*HD;
        av += sc[kbase + kk] * Vp[d];
    }
    part[qt][d] = av;
    __syncthreads();
    if (tid < HD)
        out[((size_t)(b*TT + q)) * DD + h*HD + tid] =
            (part[0][tid] + part[1][tid] + part[2][tid] + part[3][tid]) / gs;
}

// ---------------- host orchestration ---------------------------------------
static inline void run_gemm(int epi, const float* A, const float* B,
                            const float* bias, const float* R, float* C,
                            int M, int N, int K) {
    dim3 grid(N / BNt, M / BMt);
    if (epi == 0)      sgemm_kernel<0><<<grid, 256>>>(A, B, bias, R, C, M, N, K);
    else if (epi == 1) sgemm_kernel<1><<<grid, 256>>>(A, B, bias, R, C, M, N, K);
    else               sgemm_kernel<2><<<grid, 256>>>(A, B, bias, R, C, M, N, K);
}

extern "C" void kernel_launch(void* const* d_in, const int* in_sizes, int n_in,
                              void* d_out, int out_size) {
    const float* memory  = (const float*)d_in[0];
    const void*  targets = d_in[1];
    const float* tok_emb = (const float*)d_in[2];
    const float* pos_emb = (const float*)d_in[3];
    const float* sa_qkv_w = (const float*)d_in[4];
    const float* sa_qkv_b = (const float*)d_in[5];
    const float* sa_out_w = (const float*)d_in[6];
    const float* sa_out_b = (const float*)d_in[7];
    const float* ca_q_w   = (const float*)d_in[8];
    const float* ca_q_b   = (const float*)d_in[9];
    const float* ca_kv_w  = (const float*)d_in[10];
    const float* ca_kv_b  = (const float*)d_in[11];
    const float* ca_out_w = (const float*)d_in[12];
    const float* ca_out_b = (const float*)d_in[13];
    const float* ffn1_w   = (const float*)d_in[14];
    const float* ffn1_b   = (const float*)d_in[15];
    const float* ffn2_w   = (const float*)d_in[16];
    const float* ffn2_b   = (const float*)d_in[17];
    const float* ln1_g = (const float*)d_in[18];
    const float* ln1_b = (const float*)d_in[19];
    const float* ln2_g = (const float*)d_in[20];
    const float* ln2_b = (const float*)d_in[21];
    const float* ln3_g = (const float*)d_in[22];
    const float* ln3_b = (const float*)d_in[23];
    const float* normf_g = (const float*)d_in[24];
    const float* normf_b = (const float*)d_in[25];
    const float* out_w = (const float*)d_in[26];
    const float* out_b = (const float*)d_in[27];
    float* out = (float*)d_out;

    float *x, *h, *attn, *qb, *qkv, *kv, *ffn;
    cudaGetSymbolAddress((void**)&x,    g_x);
    cudaGetSymbolAddress((void**)&h,    g_h);
    cudaGetSymbolAddress((void**)&attn, g_attn);
    cudaGetSymbolAddress((void**)&qb,   g_q);
    cudaGetSymbolAddress((void**)&qkv,  g_qkv);
    cudaGetSymbolAddress((void**)&kv,   g_kv);
    cudaGetSymbolAddress((void**)&ffn,  g_ffn);

    detect_kernel<<<1, 256>>>((const int*)targets);
    embed_kernel<<<(BT*DD + 255) / 256, 256>>>(targets, tok_emb, pos_emb, x);

    dim3 agrid(TT, BB*HH);

    for (int l = 0; l < LL; l++) {
        // ---- self-attention ----
        ln_kernel<<<BT, 256>>>(x, ln1_g + l*DD, ln1_b + l*DD, h);
        run_gemm(0, h, sa_qkv_w + (size_t)l*DD*3*DD, sa_qkv_b + (size_t)l*3*DD,
                 nullptr, qkv, BT, 3*DD, DD);
        self_attn_kernel<<<agrid, 128>>>(qkv, attn);
        run_gemm(1, attn, sa_out_w + (size_t)l*DD*DD, sa_out_b + (size_t)l*DD,
                 x, x, BT, DD, DD);
        // ---- cross-attention ----
        ln_kernel<<<BT, 256>>>(x, ln2_g + l*DD, ln2_b + l*DD, h);
        run_gemm(0, h, ca_q_w + (size_t)l*DD*DD, ca_q_b + (size_t)l*DD,
                 nullptr, qb, BT, DD, DD);
        run_gemm(0, memory, ca_kv_w + (size_t)l*DD*2*DD, ca_kv_b + (size_t)l*2*DD,
                 nullptr, kv, BM_ROWS, 2*DD, DD);
        cross_attn_kernel<<<agrid, 256>>>(qb, kv, attn);
        run_gemm(1, attn, ca_out_w + (size_t)l*DD*DD, ca_out_b + (size_t)l*DD,
                 x, x, BT, DD, DD);
        // ---- FFN ----
        ln_kernel<<<BT, 256>>>(x, ln3_g + l*DD, ln3_b + l*DD, h);
        run_gemm(2, h, ffn1_w + (size_t)l*DD*4*DD, ffn1_b + (size_t)l*4*DD,
                 nullptr, ffn, BT, 4*DD, DD);
        run_gemm(1, ffn, ffn2_w + (size_t)l*4*DD*DD, ffn2_b + (size_t)l*DD,
                 x, x, BT, DD, 4*DD);
    }

    // ---- final LN + vocab head ----
    ln_kernel<<<BT, 256>>>(x, normf_g, normf_b, h);
    run_gemm(0, h, out_w, out_b, nullptr, out, BT, VV, DD);
}